// round 8
// baseline (speedup 1.0000x reference)
#include <cuda_runtime.h>
#include <cuda_bf16.h>

#define NMASKS 128
#define W      1024
#define TILE_ROWS 62
#define TILES_PER_MASK 17                    // 16 x 62 rows + 1 x 32 rows
#define NTILES (NMASKS * TILES_PER_MASK)     // 2176
#define NPBLK  888                           // 148 SMs x 6 resident blocks
#define HALO_MAX 64                          // 62 + 2 -> 8 pack iters/warp
#define STRIDE 35                            // gcd(35,32)=1 -> conflict-free

__device__ unsigned g_mA[NMASKS];            // zero-init; reset by last block
__device__ unsigned g_mC[NMASKS];
__device__ unsigned g_mP[NMASKS];
__device__ unsigned g_ticket = 0;            // reset by last block each launch
__device__ unsigned g_done = 0;              // atomicInc wrap -> self-resetting

__device__ __forceinline__ void csa(unsigned a, unsigned b, unsigned c,
                                    unsigned &s, unsigned &cy) {
    unsigned t = a ^ b;
    s  = t ^ c;
    cy = (a & b) | (t & c);
}

__global__ __launch_bounds__(256, 6)
void prior_kernel(const float* __restrict__ masks, float* __restrict__ out) {
    // Interleaved-bitplane packed rows. Group g (128 cols) occupies slots
    // 1+4g..4+4g: plane k bit l = column 128g + 4l + k.
    // Guard slot 0 == plane3 of group -1 (zero); slot 33 == plane0 of group 8.
    __shared__ unsigned srows[HALO_MAX][STRIDE];
    __shared__ int cur_tile;
    __shared__ int is_last;

    const int tid  = threadIdx.x;
    const int lane = tid & 31;
    const int wp   = tid >> 5;               // 8 warps

    // guard words: zeroed once; pack never writes slots 33/34, and slot 0 is
    // only ever rewritten with 0 (out-of-image rows)
    for (int j = tid; j < HALO_MAX; j += 256) {
        srows[j][0] = 0u; srows[j][33] = 0u; srows[j][34] = 0u;
    }

    // ---- persistent loop: dynamic tile tickets ----
    while (true) {
        if (tid == 0) cur_tile = (int)atomicAdd(&g_ticket, 1u);
        __syncthreads();                     // publishes cur_tile; guards smem reuse
        const int t = cur_tile;
        if (t >= NTILES) break;

        const int mask = t / TILES_PER_MASK;
        const int tile = t - mask * TILES_PER_MASK;
        const int r0   = tile * TILE_ROWS;
        const int rows = (tile < 16) ? TILE_ROWS : (W - 16 * TILE_ROWS); // 62|32
        const int halo = rows + 2;
        const float4* __restrict__ base =
            (const float4*)(masks + (size_t)mask * (size_t)(W * W));

        // ---- pack: batched float4 loads (8 LDG.128 in flight), then ballots ----
        for (int k = wp; k < halo; k += 8) {
            int gr = r0 - 1 + k;
            if ((unsigned)gr >= (unsigned)W) {
                srows[k][lane] = 0u;
            } else {
                const float4* __restrict__ rowp = base + (size_t)gr * (W / 4);
                float4 v[8];
                #pragma unroll
                for (int it = 0; it < 8; it++) v[it] = rowp[it * 32 + lane];
                #pragma unroll
                for (int it = 0; it < 8; it++) {
                    unsigned p0 = __ballot_sync(0xffffffffu, v[it].x > 0.0f);
                    unsigned p1 = __ballot_sync(0xffffffffu, v[it].y > 0.0f);
                    unsigned p2 = __ballot_sync(0xffffffffu, v[it].z > 0.0f);
                    unsigned p3 = __ballot_sync(0xffffffffu, v[it].w > 0.0f);
                    unsigned mine = (lane == 0) ? p0 : (lane == 1) ? p1
                                  : (lane == 2) ? p2 : p3;
                    if (lane < 4) srows[k][1 + 4 * it + lane] = mine;
                }
            }
        }
        __syncthreads();

        // ---- compute: rows x 8 groups tasks over 256 threads ----
        unsigned accA = 0, accC = 0, accP = 0;
        const int ntasks = rows * 8;         // 496 or 256
        #pragma unroll 1
        for (int base_t = 0; base_t < ntasks; base_t += 256) {
            int id = tid + base_t;
            if (id >= ntasks) break;
            int g  = id & 7;
            int r  = id >> 3;
            const unsigned* __restrict__ Tr = srows[r];
            const unsigned* __restrict__ Mr = srows[r + 1];
            const unsigned* __restrict__ Br = srows[r + 2];
            int s = 1 + 4 * g;

            unsigned T[4], M[4], B[4];
            #pragma unroll
            for (int k = 0; k < 4; k++) { T[k] = Tr[s+k]; M[k] = Mr[s+k]; B[k] = Br[s+k]; }
            unsigned Tp3 = Tr[s-1], Mp3 = Mr[s-1], Bp3 = Br[s-1];
            unsigned Tn0 = Tr[s+4], Mn0 = Mr[s+4], Bn0 = Br[s+4];

            unsigned TSL = (T[3] << 1) | (Tp3 >> 31), TSR = (T[0] >> 1) | (Tn0 << 31);
            unsigned MSL = (M[3] << 1) | (Mp3 >> 31), MSR = (M[0] >> 1) | (Mn0 << 31);
            unsigned BSL = (B[3] << 1) | (Bp3 >> 31), BSR = (B[0] >> 1) | (Bn0 << 31);

            #pragma unroll
            for (int k = 0; k < 4; k++) {
                unsigned tl = (k > 0) ? T[k-1] : TSL;
                unsigned ml = (k > 0) ? M[k-1] : MSL;
                unsigned bl = (k > 0) ? B[k-1] : BSL;
                unsigned tr = (k < 3) ? T[k+1] : TSR;
                unsigned mr = (k < 3) ? M[k+1] : MSR;
                unsigned br = (k < 3) ? B[k+1] : BSR;
                unsigned tt = T[k], bot = B[k], mid = M[k];

                unsigned s1, c1, s2, c2, s3, c3;
                csa(tl, tt, tr, s1, c1);
                csa(ml, mr, bl, s2, c2);
                csa(bot, br, s1, s3, c3);
                unsigned s4 = s2 ^ s3, c4 = s2 & s3;
                unsigned u1, v1;
                csa(c1, c2, c3, u1, v1);
                unsigned u2 = u1 ^ c4, v2 = u1 & c4;
                unsigned b0 = s4, b1 = u2, b2 = v1 ^ v2, b3 = v1 & v2;

                accA += __popc(mid);

                unsigned conn = __popc(b0 & mid) + 2u * __popc(b1 & mid)
                              + 4u * __popc(b2 & mid) + 8u * __popc(b3 & mid);
                unsigned tot  = __popc(b0) + 2u * __popc(b1)
                              + 4u * __popc(b2) + 8u * __popc(b3);
                unsigned perim = (tot - conn)
                               + 4u * __popc(b3 & mid)
                               + 2u * __popc(b2 & b1 & mid)
                               +      __popc(b2 & b0 & mid);

                accC += conn;
                accP += perim;
            }
        }

        // ---- per-tile reduction: warp reduce + direct REDG per warp ----
        accA = __reduce_add_sync(0xffffffffu, accA);
        accC = __reduce_add_sync(0xffffffffu, accC);
        accP = __reduce_add_sync(0xffffffffu, accP);
        if (lane == 0) {
            atomicAdd(&g_mA[mask], accA);
            atomicAdd(&g_mC[mask], accC);
            atomicAdd(&g_mP[mask], accP);
        }
        // loop-top __syncthreads() protects srows before next tile
    }

    // ---- completion: last finisher scores + resets state for graph replay ----
    if (tid == 0) {
        __threadfence();
        unsigned done = atomicInc(&g_done, NPBLK - 1);   // wraps to 0 itself
        is_last = (done == NPBLK - 1);
    }
    __syncthreads();

    if (is_last) {
        if (tid < NMASKS) {
            unsigned a = *(volatile unsigned*)&g_mA[tid];
            unsigned c = *(volatile unsigned*)&g_mC[tid];
            unsigned p = *(volatile unsigned*)&g_mP[tid];

            float area  = (float)a;
            float conn  = (float)c;
            float perim = (float)p;

            float safe_area  = (area > 0.0f) ? area : 1.0f;
            float area_ratio = area / (float)(W * W);
            float area_score = (area_ratio >= 0.001f && area_ratio <= 0.5f) ? 1.0f : 0.1f;

            float comp_score = (conn > 0.0f)
                ? fminf(1.0f, 10.0f / (conn / safe_area + 1e-6f))
                : 0.1f;

            float par = perim / safe_area;
            float shape_score = (area > 0.0f)
                ? ((par <= 100.0f) ? 1.0f : fmaxf(0.1f, 100.0f / (par + 1e-6f)))
                : 0.1f;

            float validity = 0.4f * area_score + 0.3f * comp_score + 0.3f * shape_score;
            out[tid] = fmaxf(0.05f, validity);

            g_mA[tid] = 0u; g_mC[tid] = 0u; g_mP[tid] = 0u;
        }
        if (tid == 0) g_ticket = 0u;
    }
}

extern "C" void kernel_launch(void* const* d_in, const int* in_sizes, int n_in,
                              void* d_out, int out_size) {
    const float* masks = (const float*)d_in[0];
    float* out = (float*)d_out;
    (void)in_sizes; (void)n_in; (void)out_size;

    prior_kernel<<<NPBLK, 256>>>(masks, out);
}

// round 9
// speedup vs baseline: 1.2565x; 1.2565x over previous
#include <cuda_runtime.h>
#include <cuda_bf16.h>

#define NMASKS 128
#define W      1024
#define STRIP_ROWS 64
#define STRIPS_PER_MASK (W / STRIP_ROWS)      // 16
#define NSTRIPS (NMASKS * STRIPS_PER_MASK)    // 2048 warps
#define NBLOCKS (NSTRIPS / 8)                 // 256 blocks x 8 warps

__device__ unsigned g_mA[NMASKS];             // zero-init; reset by last warp
__device__ unsigned g_mC[NMASKS];
__device__ unsigned g_mP[NMASKS];
__device__ unsigned g_done = 0;               // atomicInc wrap -> self-resetting

struct PRow { unsigned w, lw, rw; };

__device__ __forceinline__ void csa(unsigned a, unsigned b, unsigned c,
                                    unsigned &s, unsigned &cy) {
    unsigned t = a ^ b;
    s  = t ^ c;
    cy = (a & b) | (t & c);
}

// 8 streaming LDG.128 for one full 1024-col row (coalesced: lanes consecutive 16B)
__device__ __forceinline__ void load_row(float4 v[8], const float4* __restrict__ rb,
                                         int row, int lane) {
    const float4* __restrict__ p = rb + (size_t)row * (W / 4) + lane;
    #pragma unroll
    for (int it = 0; it < 8; it++) v[it] = __ldcs(p + it * 32);
}

// Interleaved-bitplane pack: lane l owns word l = plane (l&3) of 128-col group (l>>2);
// bit b of word l = column 128*(l>>2) + 4*b + (l&3). Also precompute the per-lane
// left/right column-neighbor words (shift rules differ for plane 0 / plane 3).
__device__ __forceinline__ PRow pack_row(const float4 v[8], int lane) {
    unsigned wd = 0;
    #pragma unroll
    for (int it = 0; it < 8; it++) {
        unsigned b0 = __ballot_sync(0xffffffffu, v[it].x > 0.0f);
        unsigned b1 = __ballot_sync(0xffffffffu, v[it].y > 0.0f);
        unsigned b2 = __ballot_sync(0xffffffffu, v[it].z > 0.0f);
        unsigned b3 = __ballot_sync(0xffffffffu, v[it].w > 0.0f);
        wd = (lane == 4 * it + 0) ? b0 : wd;
        wd = (lane == 4 * it + 1) ? b1 : wd;
        wd = (lane == 4 * it + 2) ? b2 : wd;
        wd = (lane == 4 * it + 3) ? b3 : wd;
    }
    unsigned l1 = __shfl_sync(0xffffffffu, wd, lane - 1);  // wraps at lane 0
    unsigned r1 = __shfl_sync(0xffffffffu, wd, lane + 1);  // wraps at lane 31
    unsigned l3 = __shfl_sync(0xffffffffu, wd, lane + 3);  // plane3 same group (k==0)
    unsigned r3 = __shfl_sync(0xffffffffu, wd, lane - 3);  // plane0 same group (k==3)
    if (lane == 0)  l1 = 0u;   // group -1 guard
    if (lane == 31) r1 = 0u;   // group  8 guard
    int k = lane & 3;
    PRow pr;
    pr.w  = wd;
    pr.lw = (k == 0) ? ((l3 << 1) | (l1 >> 31)) : l1;
    pr.rw = (k == 3) ? ((r3 >> 1) | (r1 << 31)) : r1;
    return pr;
}

__device__ __forceinline__ void compute_row(const PRow &A, const PRow &B, const PRow &C,
                                            unsigned &accA, unsigned &accC, unsigned &accP) {
    unsigned tl = A.lw, tt = A.w,  tr = A.rw;
    unsigned ml = B.lw, mid = B.w, mr = B.rw;
    unsigned bl = C.lw, bot = C.w, br = C.rw;

    // CSA tree: per-bit 3x3-ring neighbor count (0..8) as bitplanes b0..b3
    unsigned s1, c1, s2, c2, s3, c3;
    csa(tl, tt, tr, s1, c1);
    csa(ml, mr, bl, s2, c2);
    csa(bot, br, s1, s3, c3);
    unsigned s4 = s2 ^ s3, c4 = s2 & s3;
    unsigned u1, v1;
    csa(c1, c2, c3, u1, v1);
    unsigned u2 = u1 ^ c4, v2 = u1 & c4;
    unsigned b0 = s4, b1 = u2, b2 = v1 ^ v2, b3 = v1 & v2;

    accA += __popc(mid);

    unsigned conn = __popc(b0 & mid) + 2u * __popc(b1 & mid)
                  + 4u * __popc(b2 & mid) + 8u * __popc(b3 & mid);
    unsigned tot  = __popc(b0) + 2u * __popc(b1)
                  + 4u * __popc(b2) + 8u * __popc(b3);
    unsigned perim = (tot - conn)
                   + 4u * __popc(b3 & mid)
                   + 2u * __popc(b2 & b1 & mid)
                   +      __popc(b2 & b0 & mid);
    accC += conn;
    accP += perim;
}

__global__ __launch_bounds__(256, 2)
void prior_kernel(const float* __restrict__ masks, float* __restrict__ out) {
    const int tid  = threadIdx.x;
    const int lane = tid & 31;
    const int wid  = blockIdx.x * 8 + (tid >> 5);   // global warp id == strip id

    const int mask = wid >> 4;                      // 16 strips per mask
    const int s0   = (wid & 15) * STRIP_ROWS;       // 0..960
    const float4* __restrict__ rb =
        (const float4*)masks + (size_t)mask * (size_t)(W * W / 4);

    float4 v[8], u[8];
    PRow A, B, C;

    // ---- prologue: pack rows s0-1, s0; prefetch row s0+1 ----
    if (s0 > 0) { load_row(v, rb, s0 - 1, lane); A = pack_row(v, lane); }
    else        { A.w = 0u; A.lw = 0u; A.rw = 0u; }
    load_row(v, rb, s0, lane);
    B = pack_row(v, lane);
    load_row(v, rb, s0 + 1, lane);                  // s0+1 <= 961, always valid

    unsigned accA = 0, accC = 0, accP = 0;

    // ---- barrier-free rolling loop: loads for row r+2 in flight during row r ----
    #pragma unroll 1
    for (int i = 0; i < STRIP_ROWS; i += 2) {
        int r = s0 + i;

        // body 0: prefetch row r+2 into u; consume v (row r+1, always valid)
        bool pv = (r + 2 < W);                      // r+2 <= s0+64 by construction
        if (pv) load_row(u, rb, r + 2, lane);
        C = pack_row(v, lane);
        compute_row(A, B, C, accA, accC, accP);
        A = B; B = C;

        // body 1: prefetch row r+3 into v; consume u (row r+2)
        bool pv2 = (i + 3 <= STRIP_ROWS) && (r + 3 < W);
        if (pv2) load_row(v, rb, r + 3, lane);
        if (pv) { C = pack_row(u, lane); }
        else    { C.w = 0u; C.lw = 0u; C.rw = 0u; }
        compute_row(A, B, C, accA, accC, accP);
        A = B; B = C;
    }

    // ---- per-strip reduction: warp reduce + 3 REDG ----
    accA = __reduce_add_sync(0xffffffffu, accA);
    accC = __reduce_add_sync(0xffffffffu, accC);
    accP = __reduce_add_sync(0xffffffffu, accP);

    unsigned done = 0;
    if (lane == 0) {
        atomicAdd(&g_mA[mask], accA);
        atomicAdd(&g_mC[mask], accC);
        atomicAdd(&g_mP[mask], accP);
        __threadfence();
        done = atomicInc(&g_done, NSTRIPS - 1);     // wraps to 0 -> replayable
    }
    done = __shfl_sync(0xffffffffu, done, 0);

    // ---- last warp: score all masks (4 per lane) + reset for graph replay ----
    if (done == NSTRIPS - 1) {
        #pragma unroll
        for (int j = 0; j < 4; j++) {
            int m = lane + j * 32;
            unsigned a = *(volatile unsigned*)&g_mA[m];
            unsigned c = *(volatile unsigned*)&g_mC[m];
            unsigned p = *(volatile unsigned*)&g_mP[m];

            float area  = (float)a;
            float conn  = (float)c;
            float perim = (float)p;

            float safe_area  = (area > 0.0f) ? area : 1.0f;
            float area_ratio = area / (float)(W * W);
            float area_score = (area_ratio >= 0.001f && area_ratio <= 0.5f) ? 1.0f : 0.1f;

            float comp_score = (conn > 0.0f)
                ? fminf(1.0f, 10.0f / (conn / safe_area + 1e-6f))
                : 0.1f;

            float par = perim / safe_area;
            float shape_score = (area > 0.0f)
                ? ((par <= 100.0f) ? 1.0f : fmaxf(0.1f, 100.0f / (par + 1e-6f)))
                : 0.1f;

            float validity = 0.4f * area_score + 0.3f * comp_score + 0.3f * shape_score;
            out[m] = fmaxf(0.05f, validity);

            g_mA[m] = 0u; g_mC[m] = 0u; g_mP[m] = 0u;
        }
    }
}

extern "C" void kernel_launch(void* const* d_in, const int* in_sizes, int n_in,
                              void* d_out, int out_size) {
    const float* masks = (const float*)d_in[0];
    float* out = (float*)d_out;
    (void)in_sizes; (void)n_in; (void)out_size;

    prior_kernel<<<NBLOCKS, 256>>>(masks, out);
}